// round 8
// baseline (speedup 1.0000x reference)
#include <cuda_runtime.h>
#include <float.h>

// Problem constants (fixed: B=4, M=1024, N=32768)
#define BB 4
#define MM 1024
#define NN 32768
#define NPAIRS (NN / 2)        // 16384 point-pairs per batch
#define NCHUNK 148             // chunks per batch; 148*4 = 592 blocks = exactly 4/SM, 1 wave
#define TILE 111               // ceil(16384/148); tail clamped at copy time
#define KT 8                   // keypoints per thread
#define NTHREADS 128           // 128 * 8 = 1024 = all keypoints per block
#define NROWS (BB * MM)        // 4096
#define NBLOCKS (NCHUNK * BB)  // 592

typedef unsigned long long u64;

// Zero-initialized device state; the last block self-cleans it every run, so it
// is correct on the first call and on every graph replay. No cudaMalloc anywhere.
__device__ unsigned g_rowmin[NROWS];  // ordered-uint keys: larger key == smaller v
__device__ unsigned g_done;           // completed-block counter

// ---- packed f32x2 helpers (Blackwell FFMA2 path) ----
__device__ __forceinline__ u64 fma2(u64 a, u64 b, u64 c) {
    u64 d; asm("fma.rn.f32x2 %0, %1, %2, %3;" : "=l"(d) : "l"(a), "l"(b), "l"(c));
    return d;
}
__device__ __forceinline__ u64 mul2(u64 a, u64 b) {
    u64 d; asm("mul.rn.f32x2 %0, %1, %2;" : "=l"(d) : "l"(a), "l"(b));
    return d;
}
__device__ __forceinline__ u64 dup2(float x) {
    u64 d; asm("mov.b64 %0, {%1, %1};" : "=l"(d) : "f"(x));
    return d;
}
__device__ __forceinline__ void unpack2(u64 v, float& lo, float& hi) {
    asm("mov.b64 {%0, %1}, %2;" : "=f"(lo), "=f"(hi) : "l"(v));
}

// Monotone DECREASING float->uint key: x1 < x2  <=>  key(x1) > key(x2).
// key = ~flip(u), flip(u) = (u>>31) ? ~u : u|0x80000000. Key 0 loses to all reals.
__device__ __forceinline__ unsigned enc_min(float v) {
    unsigned u = __float_as_uint(v);
    unsigned flip = ((int)u < 0) ? ~u : (u | 0x80000000u);
    return ~flip;
}
__device__ __forceinline__ float dec_min(unsigned key) {
    unsigned flip = ~key;
    unsigned u = (flip & 0x80000000u) ? (flip ^ 0x80000000u) : ~flip;
    return __uint_as_float(u);
}

// --- Single fused kernel ---
// Phase 1 (all 592 blocks): per (chunk, b), min over the chunk's points for all 1024
//   keypoints of batch b; REDG.MAX encoded mins into g_rowmin (order-independent).
// Phase 2 (last block only): decode row mins, d = sqrt(max(|k|^2 + v, 0)), mean,
//   write out, and reset g_rowmin/g_done for the next replay.
__global__ void __launch_bounds__(NTHREADS, 4)
fused_kernel(const float* __restrict__ kpt, const float* __restrict__ pc,
             float* __restrict__ out) {
    const int chunk = blockIdx.x;
    const int b     = blockIdx.y;
    const int t     = threadIdx.x;
    const int m0    = t * KT;

    // smem: per pair i: s_pts[2i]={x2,y2}, s_pts[2i+1]={z2,pp}  (two LDS.128 per iter)
    __shared__ ulonglong2 s_pts[2 * TILE];
    __shared__ unsigned s_last;
    __shared__ float s_red[NTHREADS / 32];

    // Copy phase: stage this chunk's point-pairs + packed |p|^2 (computed once).
    if (t < TILE) {
        int q = min(chunk * TILE + t, NPAIRS - 1);  // tail clamp: dup pair is a min no-op
        const float* pcb = pc + (size_t)b * 3 * NN;
        u64 x2 = ((const u64*)pcb)[q];
        u64 y2 = ((const u64*)(pcb + NN))[q];
        u64 z2 = ((const u64*)(pcb + 2 * NN))[q];
        u64 pp = fma2(z2, z2, fma2(y2, y2, mul2(x2, x2)));  // (|p0|^2, |p1|^2)
        ulonglong2 a, c;
        a.x = x2; a.y = y2;
        c.x = z2; c.y = pp;
        s_pts[2 * t]     = a;
        s_pts[2 * t + 1] = c;
    }

    // Per-thread keypoints, scaled by -2, duplicated into both f32x2 halves (hoisted).
    const float* kb = kpt + (size_t)b * 3 * MM;
    u64 knx[KT], kny[KT], knz[KT];
    float mnl[KT], mnh[KT];
#pragma unroll
    for (int j = 0; j < KT; j++) {
        knx[j] = dup2(-2.0f * kb[m0 + j]);
        kny[j] = dup2(-2.0f * kb[MM + m0 + j]);
        knz[j] = dup2(-2.0f * kb[2 * MM + m0 + j]);
        mnl[j] = FLT_MAX;
        mnh[j] = FLT_MAX;
    }
    __syncthreads();

    // Main loop: pure compute against smem (broadcast LDS, conflict-free).
#pragma unroll 3
    for (int i = 0; i < TILE; i++) {
        ulonglong2 a = s_pts[2 * i];      // (x2, y2)
        ulonglong2 c = s_pts[2 * i + 1];  // (z2, pp)
#pragma unroll
        for (int j = 0; j < KT; j++) {
            u64 v = fma2(knx[j], a.x, fma2(kny[j], a.y, fma2(knz[j], c.x, c.y)));
            float lo, hi;
            unpack2(v, lo, hi);  // register-pair aliasing, no real MOVs
            mnl[j] = fminf(mnl[j], lo);
            mnh[j] = fminf(mnh[j], hi);
        }
    }

    // Fire-and-forget REDG.MAX per keypoint (order-independent => deterministic).
    unsigned* rp = g_rowmin + b * MM + m0;
#pragma unroll
    for (int j = 0; j < KT; j++)
        atomicMax(rp + j, enc_min(fminf(mnl[j], mnh[j])));

    // Last-block election (threadFenceReduction pattern).
    __threadfence();
    __syncthreads();
    if (t == 0) {
        unsigned old = atomicAdd(&g_done, 1u);
        s_last = (old == NBLOCKS - 1) ? 1u : 0u;
    }
    __syncthreads();
    if (!s_last) return;

    // Phase 2: final reduction by the last block (reads L2 where the REDGs landed),
    // with self-cleaning of the table for the next graph replay.
    float sum = 0.0f;
#pragma unroll
    for (int rr = 0; rr < NROWS / NTHREADS; rr++) {  // 32 coalesced rounds
        int r = rr * NTHREADS + t;
        float v = dec_min(__ldcg(g_rowmin + r));
        __stcg(g_rowmin + r, 0u);  // reset for next replay
        int bb = r >> 10, m = r & (MM - 1);
        const float* kr = kpt + (size_t)bb * 3 * MM;
        float x = kr[m], y = kr[MM + m], z = kr[2 * MM + m];
        sum += sqrtf(fmaxf(v + (x * x + y * y + z * z), 0.0f));
    }
    // Block reduce: warp shfl then cross-warp via smem.
#pragma unroll
    for (int off = 16; off; off >>= 1) sum += __shfl_xor_sync(0xffffffffu, sum, off);
    int warp = t >> 5, lane = t & 31;
    if (lane == 0) s_red[warp] = sum;
    __syncthreads();
    if (t == 0) {
        float s = 0.0f;
#pragma unroll
        for (int w = 0; w < NTHREADS / 32; w++) s += s_red[w];
        *out = s * (1.0f / (float)NROWS);
        g_done = 0;  // reset counter for next replay
    }
}

extern "C" void kernel_launch(void* const* d_in, const int* in_sizes, int n_in,
                              void* d_out, int out_size) {
    const float* keypoints = (const float*)d_in[0];  // [B,3,M]
    const float* pc        = (const float*)d_in[1];  // [B,3,N]
    float* out             = (float*)d_out;          // scalar

    (void)in_sizes; (void)n_in; (void)out_size;

    dim3 grid(NCHUNK, BB);
    fused_kernel<<<grid, NTHREADS>>>(keypoints, pc, out);
}

// round 9
// speedup vs baseline: 1.3571x; 1.3571x over previous
#include <cuda_runtime.h>
#include <float.h>

// Problem constants (fixed: B=4, M=1024, N=32768)
#define BB 4
#define MM 1024
#define NN 32768
#define NPAIRS (NN / 2)        // 16384 point-pairs per batch
#define NCHUNK 148             // chunks per batch; 148*4 = 592 blocks = exactly 4/SM, 1 wave
#define TILE 111               // ceil(16384/148); tail clamped at copy time
#define KT 8                   // keypoints per thread
#define NTHREADS 128           // 128 * 8 = 1024 = all keypoints per block
#define NROWS (BB * MM)        // 4096
#define FBLOCKS 16             // final kernel blocks (256 threads each -> 4096 rows)

typedef unsigned long long u64;

// Scratch (no cudaMalloc allowed). Chunk-major: [chunk][b*MM+m]
//  -> min_kernel stores coalesced float4; final kernel loads coalesced across lanes.
__device__ float g_partial[NCHUNK * NROWS];
__device__ float g_bsum[FBLOCKS];
__device__ unsigned g_done;   // zero-init at load; last block resets -> replay-safe

// ---- packed f32x2 helpers (Blackwell FFMA2 path) ----
__device__ __forceinline__ u64 fma2(u64 a, u64 b, u64 c) {
    u64 d; asm("fma.rn.f32x2 %0, %1, %2, %3;" : "=l"(d) : "l"(a), "l"(b), "l"(c));
    return d;
}
__device__ __forceinline__ u64 mul2(u64 a, u64 b) {
    u64 d; asm("mul.rn.f32x2 %0, %1, %2;" : "=l"(d) : "l"(a), "l"(b));
    return d;
}
__device__ __forceinline__ u64 dup2(float x) {
    u64 d; asm("mov.b64 %0, {%1, %1};" : "=l"(d) : "f"(x));
    return d;
}
__device__ __forceinline__ void unpack2(u64 v, float& lo, float& hi) {
    asm("mov.b64 {%0, %1}, %2;" : "=f"(lo), "=f"(hi) : "l"(v));
}

// --- Kernel 1 (UNCHANGED from the 21.7us R3 version): per (chunk, b) block:
// min over chunk's points for all 1024 keypoints. v = |p|^2 - 2 k.p
__global__ void __launch_bounds__(NTHREADS, 4)
min_kernel(const float* __restrict__ kpt, const float* __restrict__ pc) {
    const int chunk = blockIdx.x;
    const int b     = blockIdx.y;
    const int t     = threadIdx.x;
    const int m0    = t * KT;

    // smem: per pair i: s_pts[2i]={x2,y2}, s_pts[2i+1]={z2,pp}  (two LDS.128 per iter)
    __shared__ ulonglong2 s_pts[2 * TILE];

    // Copy phase: stage this chunk's point-pairs + packed |p|^2 (computed once).
    if (t < TILE) {
        int q = min(chunk * TILE + t, NPAIRS - 1);  // tail clamp: dup pair is a min no-op
        const float* pcb = pc + (size_t)b * 3 * NN;
        u64 x2 = ((const u64*)pcb)[q];
        u64 y2 = ((const u64*)(pcb + NN))[q];
        u64 z2 = ((const u64*)(pcb + 2 * NN))[q];
        u64 pp = fma2(z2, z2, fma2(y2, y2, mul2(x2, x2)));  // (|p0|^2, |p1|^2)
        ulonglong2 a, c;
        a.x = x2; a.y = y2;
        c.x = z2; c.y = pp;
        s_pts[2 * t]     = a;
        s_pts[2 * t + 1] = c;
    }

    // Per-thread keypoints, scaled by -2, duplicated into both f32x2 halves (hoisted).
    const float* kb = kpt + (size_t)b * 3 * MM;
    u64 knx[KT], kny[KT], knz[KT];
    float mnl[KT], mnh[KT];
#pragma unroll
    for (int j = 0; j < KT; j++) {
        knx[j] = dup2(-2.0f * kb[m0 + j]);
        kny[j] = dup2(-2.0f * kb[MM + m0 + j]);
        knz[j] = dup2(-2.0f * kb[2 * MM + m0 + j]);
        mnl[j] = FLT_MAX;
        mnh[j] = FLT_MAX;
    }
    __syncthreads();

    // Main loop: pure compute against smem (broadcast LDS, conflict-free).
#pragma unroll 3
    for (int i = 0; i < TILE; i++) {
        ulonglong2 a = s_pts[2 * i];      // (x2, y2)
        ulonglong2 c = s_pts[2 * i + 1];  // (z2, pp)
#pragma unroll
        for (int j = 0; j < KT; j++) {
            u64 v = fma2(knx[j], a.x, fma2(kny[j], a.y, fma2(knz[j], c.x, c.y)));
            float lo, hi;
            unpack2(v, lo, hi);  // register-pair aliasing, no real MOVs
            mnl[j] = fminf(mnl[j], lo);
            mnh[j] = fminf(mnh[j], hi);
        }
    }

    // Coalesced store: 8 consecutive floats per thread (two STG.128).
    float* outp = g_partial + (size_t)chunk * NROWS + b * MM + m0;
    float4 o0, o1;
    o0.x = fminf(mnl[0], mnh[0]);
    o0.y = fminf(mnl[1], mnh[1]);
    o0.z = fminf(mnl[2], mnh[2]);
    o0.w = fminf(mnl[3], mnh[3]);
    o1.x = fminf(mnl[4], mnh[4]);
    o1.y = fminf(mnl[5], mnh[5]);
    o1.z = fminf(mnl[6], mnh[6]);
    o1.w = fminf(mnl[7], mnh[7]);
    ((float4*)outp)[0] = o0;
    ((float4*)outp)[1] = o1;
}

// --- Kernel 2: one thread per row; chunk-loop is COALESCED across lanes.
// Then block sums + last-block fixed-order fold (deterministic) -> mean.
__global__ void __launch_bounds__(256)
final_kernel(const float* __restrict__ kpt, float* __restrict__ out) {
    const int t = threadIdx.x;
    const int r = blockIdx.x * 256 + t;            // 16*256 = 4096 rows

    float v = FLT_MAX;
#pragma unroll 8
    for (int c = 0; c < NCHUNK; c++)
        v = fminf(v, __ldcg(g_partial + (size_t)c * NROWS + r));  // L2-resident, MLP=8

    const int b = r >> 10, m = r & (MM - 1);
    const float* kb = kpt + (size_t)b * 3 * MM;
    float x = kb[m], y = kb[MM + m], z = kb[2 * MM + m];
    float sum = sqrtf(fmaxf(v + (x * x + y * y + z * z), 0.0f));

    // Block reduce (warp shfl + smem), fixed order -> deterministic.
#pragma unroll
    for (int off = 16; off; off >>= 1) sum += __shfl_xor_sync(0xffffffffu, sum, off);
    __shared__ float s_warp[8];
    __shared__ unsigned s_last;
    int warp = t >> 5, lane = t & 31;
    if (lane == 0) s_warp[warp] = sum;
    __syncthreads();
    if (t == 0) {
        float s = 0.0f;
#pragma unroll
        for (int w = 0; w < 8; w++) s += s_warp[w];
        g_bsum[blockIdx.x] = s;
        __threadfence();
        unsigned old = atomicAdd(&g_done, 1u);
        s_last = (old == FBLOCKS - 1) ? 1u : 0u;
    }
    __syncthreads();
    if (t == 0 && s_last) {
        float s = 0.0f;
#pragma unroll
        for (int i = 0; i < FBLOCKS; i++) s += g_bsum[i];  // fixed order
        *out = s * (1.0f / (float)NROWS);
        g_done = 0;  // reset for next graph replay
    }
}

extern "C" void kernel_launch(void* const* d_in, const int* in_sizes, int n_in,
                              void* d_out, int out_size) {
    const float* keypoints = (const float*)d_in[0];  // [B,3,M]
    const float* pc        = (const float*)d_in[1];  // [B,3,N]
    float* out             = (float*)d_out;          // scalar

    (void)in_sizes; (void)n_in; (void)out_size;

    dim3 grid(NCHUNK, BB);
    min_kernel<<<grid, NTHREADS>>>(keypoints, pc);
    final_kernel<<<FBLOCKS, 256>>>(keypoints, out);
}